// round 17
// baseline (speedup 1.0000x reference)
#include <cuda_runtime.h>
#include <cstdint>

// Problem constants (fixed by the reference: T=8, x shape [T*32, 128, 32, 32])
#define T_STEPS   8
#define BATCH     32
#define CHANNELS  128
#define HW        1024                      // 32*32
#define N_ELEM    (BATCH*CHANNELS*HW)       // 4,194,304 spatial positions
#define GRID1     1024                      // single wave; all blocks co-resident
#define SLABS_PER_BLOCK 4                   // slabs b, b+1024, b+2048, b+3072 share channel b%128
#define T_PINNED  5                         // timesteps 0..4 (80 MiB) pinned in L2

// Scratch (static device globals — no runtime allocation permitted).
// g_arrive is MONOTONIC across graph replays (each replay adds exactly GRID1
// arrivals) -> no reset, fully deterministic.
__device__ float    g_partials[GRID1];
__device__ unsigned g_arrive = 0;

// L2 policy hints (policy-register form works at 128-bit width).
__device__ __forceinline__ uint64_t make_policy_evict_first() {
    uint64_t p;
    asm("createpolicy.fractional.L2::evict_first.b64 %0, 1.0;" : "=l"(p));
    return p;
}
__device__ __forceinline__ uint64_t make_policy_evict_last() {
    uint64_t p;
    asm("createpolicy.fractional.L2::evict_last.b64 %0, 1.0;" : "=l"(p));
    return p;
}
// x: single-use stream -> evict_first (don't displace the resident output).
__device__ __forceinline__ float4 ld_stream(const float* p, uint64_t pol) {
    float4 v;
    asm volatile("ld.global.nc.L2::cache_hint.v4.f32 {%0,%1,%2,%3}, [%4], %5;"
                 : "=f"(v.x), "=f"(v.y), "=f"(v.z), "=f"(v.w)
                 : "l"(p), "l"(pol));
    return v;
}
// out, pinned slice (t < T_PINNED): stays resident in L2 across replays.
__device__ __forceinline__ void st_resident(float* p, float4 v, uint64_t pol) {
    asm volatile("st.global.L2::cache_hint.v4.f32 [%0], {%1,%2,%3,%4}, %5;"
                 :: "l"(p), "f"(v.x), "f"(v.y), "f"(v.z), "f"(v.w), "l"(pol)
                 : "memory");
}
// out, streamed slice (t >= T_PINNED): default policy, doesn't thrash the pinned set.
__device__ __forceinline__ void st_normal(float* p, float4 v) {
    asm volatile("st.global.v4.f32 [%0], {%1,%2,%3,%4};"
                 :: "l"(p), "f"(v.x), "f"(v.y), "f"(v.z), "f"(v.w)
                 : "memory");
}
__device__ __forceinline__ void st_out(float* p, float4 v, int t, uint64_t pol_last) {
    if (t < T_PINNED) st_resident(p, v, pol_last);
    else              st_normal(p, v);
}

// Block-wide deterministic sum (256 threads): shuffle tree + one smem hop.
__device__ __forceinline__ float block_sum_256(float v, float* ws) {
#pragma unroll
    for (int off = 16; off > 0; off >>= 1)
        v += __shfl_down_sync(0xFFFFFFFFu, v, off);
    const int wid = threadIdx.x >> 5;
    if ((threadIdx.x & 31) == 0) ws[wid] = v;
    __syncthreads();
    if (wid == 0) {
        v = (threadIdx.x < 8) ? ws[threadIdx.x] : 0.0f;
#pragma unroll
        for (int off = 4; off > 0; off >>= 1)
            v += __shfl_down_sync(0xFFFFFFFFu, v, off);
    }
    __syncthreads();
    return v;                 // valid in thread 0
}

// ---------------------------------------------------------------------------
// Fused persistent kernel:
//   Phase A: IF recurrence (hoisted MLP=8 loads) -> bits in smem, partials.
//   After arrival, BEFORE the spin: write all-zero 128B output lines (~44% of
//   (line,t) pairs; detected by ballot over 8-thread groups). These are
//   scale-independent and line-complete -> fills the barrier hole with useful
//   write transit without breaking line coherence (R13's failure mode).
//   Spin on arrivals -> redundant per-block scale finalization.
//   Phase B: write only spike-containing lines (full lines, float4/thread).
// Every output line is written exactly once. Split L2 policy: t<5 pinned.
// ---------------------------------------------------------------------------
__global__ __launch_bounds__(256, 8) void if_fused(const float* __restrict__ x,
                                                   const float* __restrict__ thresh,
                                                   float* __restrict__ out) {
    __shared__ uint32_t s_bits[SLABS_PER_BLOCK][256];   // packed spike bytes, 4 KiB
    __shared__ float    s_ws[8];
    __shared__ float    s_scale;
    __shared__ unsigned s_gen;

    const float    thre      = __ldg(thresh);
    const uint64_t pol_first = make_policy_evict_first();
    const uint64_t pol_last  = make_policy_evict_last();
    const float4   zero4     = make_float4(0.0f, 0.0f, 0.0f, 0.0f);
    const int      lane      = threadIdx.x & 31;
    const int      grp8      = (lane >> 3) * 8;         // ballot shift for 8-thread group
    float local = 0.0f;

    // ---- Phase A: recurrence over 4 same-channel slabs ----
#pragma unroll 1
    for (int k = 0; k < SLABS_PER_BLOCK; k++) {
        const int slab = blockIdx.x + k * GRID1;
        const int n    = slab * HW + threadIdx.x * 4;

        float4 xv[T_STEPS];
#pragma unroll
        for (int t = 0; t < T_STEPS; t++)
            xv[t] = ld_stream(x + (size_t)t * N_ELEM + n, pol_first);

        float    mem[4] = {0.5f * thre, 0.5f * thre, 0.5f * thre, 0.5f * thre};
        unsigned sb[4]  = {0u, 0u, 0u, 0u};

#pragma unroll
        for (int t = 0; t < T_STEPS; t++) {
            const float v[4] = {xv[t].x, xv[t].y, xv[t].z, xv[t].w};
#pragma unroll
            for (int j = 0; j < 4; j++) {
                mem[j] += v[j];
                if (mem[j] >= thre) {          // heaviside(mem - cur)
                    mem[j] -= thre;            // mem -= s*cur
                    sb[j]  |= (1u << t);
                }
            }
        }

        s_bits[k][threadIdx.x] = sb[0] | (sb[1] << 8) | (sb[2] << 16) | (sb[3] << 24);

        // Compensation pass -> per-element new_thre (cnt via popc).
#pragma unroll
        for (int j = 0; j < 4; j++) {
            const int   cnt = __popc(sb[j]);
            const float cv  = fminf((mem[j] - 0.5f * thre) + (float)cnt * thre,
                                    (float)T_STEPS * thre);
            if (cv > 0.0f && cnt > 0)
                local += cv / (float)cnt;
        }
    }

    const float total = block_sum_256(local, s_ws);

    // ---- Arrive (monotonic generations) ----
    if (threadIdx.x == 0) {
        g_partials[blockIdx.x] = total;
        __threadfence();
        const unsigned old = atomicAdd(&g_arrive, 1u);
        s_gen = old / GRID1;                    // this replay's generation
    }
    __syncthreads();

    // ---- Hole filler: write all-zero 128B lines now (scale-independent) ----
#pragma unroll 1
    for (int k = 0; k < SLABS_PER_BLOCK; k++) {
        const uint32_t bits = s_bits[k][threadIdx.x];
        // spike-times mask over this thread's 4 elements
        const unsigned tmask = (bits | (bits >> 8) | (bits >> 16) | (bits >> 24)) & 0xFFu;
        const int      slab  = blockIdx.x + k * GRID1;
        const int      n     = slab * HW + threadIdx.x * 4;
#pragma unroll
        for (int t = 0; t < T_STEPS; t++) {
            const unsigned m   = __ballot_sync(0xFFFFFFFFu, (tmask >> t) & 1u);
            const unsigned grp = (m >> grp8) & 0xFFu;   // 8 threads = one 128B line
            if (grp == 0u)                               // whole line is zero: final
                st_out(out + (size_t)t * N_ELEM + n, zero4, t, pol_last);
        }
    }

    // ---- Spin for all arrivals ----
    if (threadIdx.x == 0) {
        const unsigned target = (s_gen + 1u) * GRID1;
        unsigned v;
        for (;;) {
            asm volatile("ld.acquire.gpu.u32 %0, [%1];" : "=r"(v)
                         : "l"(&g_arrive) : "memory");
            if (v >= target) break;
            __nanosleep(256);
        }
    }
    __syncthreads();

    // ---- Redundant local finalization (identical fixed order per block) ----
    {
        float contrib = 0.0f;
        if (threadIdx.x < CHANNELS) {
            float s = 0.0f;
#pragma unroll
            for (int j = 0; j < GRID1 / CHANNELS; j++)
                s += g_partials[threadIdx.x + j * CHANNELS];
            const float ub = s / (float)(BATCH * HW);
            contrib = (thre > ub) ? (ub - thre) : 0.0f;
        }
        const float tot = block_sum_256(contrib, s_ws);
        if (threadIdx.x == 0)
            s_scale = thre + 0.2f * tot / (float)CHANNELS;   // LR*2 = 0.2
    }
    __syncthreads();

    // ---- Phase B: write the spike-containing lines (full lines) ----
    const float scale = s_scale;
#pragma unroll 1
    for (int k = 0; k < SLABS_PER_BLOCK; k++) {
        const uint32_t bits  = s_bits[k][threadIdx.x];
        const unsigned tmask = (bits | (bits >> 8) | (bits >> 16) | (bits >> 24)) & 0xFFu;
        const int      slab  = blockIdx.x + k * GRID1;
        const int      n     = slab * HW + threadIdx.x * 4;
#pragma unroll
        for (int t = 0; t < T_STEPS; t++) {
            const unsigned m   = __ballot_sync(0xFFFFFFFFu, (tmask >> t) & 1u);
            const unsigned grp = (m >> grp8) & 0xFFu;
            if (grp != 0u) {                  // line has spikes: write full line
                float4 o;
                o.x = ((bits >> (t))      & 1u) ? scale : 0.0f;
                o.y = ((bits >> (t + 8))  & 1u) ? scale : 0.0f;
                o.z = ((bits >> (t + 16)) & 1u) ? scale : 0.0f;
                o.w = ((bits >> (t + 24)) & 1u) ? scale : 0.0f;
                st_out(out + (size_t)t * N_ELEM + n, o, t, pol_last);
            }
        }
    }
}

// ---------------------------------------------------------------------------
extern "C" void kernel_launch(void* const* d_in, const int* in_sizes, int n_in,
                              void* d_out, int out_size) {
    const float* x      = (const float*)d_in[0];   // [T*B, C, H, W] fp32
    const float* thresh = (const float*)d_in[1];   // [1] fp32
    float*       out    = (float*)d_out;

    if_fused<<<GRID1, 256>>>(x, thresh, out);
}